// round 9
// baseline (speedup 1.0000x reference)
#include <cuda_runtime.h>
#include <cstddef>

#define Bb   64
#define Tt   64
#define DIN  188
#define HH   192
#define NACT 576       // 256 push + 64 pop + 256 repl
#define TILE 256

// Scratch
__device__ float g_actions[Bb * NACT];          // UNNORMALIZED exp(logit)
__device__ float g_esum[Bb];                    // softmax denominators
__device__ float g_hn[Bb * HH];
__device__ float g_tmp[(size_t)Bb * Tt * 64];   // tmp[b,k,u,y,r] (unnormalized)
__device__ float g_alphaT[Bb * 16];
__device__ unsigned int g_done = 0;

// ---------------------------------------------------------------------------
// K1a: h_new (warp-per-row, 16 warps x 12 rows); also alpha copy + zero scratch
// ---------------------------------------------------------------------------
__global__ void __launch_bounds__(512) k1a_rnn(
    const float* __restrict__ x, const float* __restrict__ h,
    const float* __restrict__ top, const float* __restrict__ Wih,
    const float* __restrict__ bih, const float* __restrict__ Whh,
    const float* __restrict__ bhh, const float* __restrict__ alpha,
    float* __restrict__ out_h, float* __restrict__ out_alpha)
{
    const int b = blockIdx.x;
    const int t = threadIdx.x;
    const int w = t >> 5, lane = t & 31;
    __shared__ float xin[HH], hS[HH];

    if (t < 256) {
        const float4* a4 = (const float4*)(alpha + (size_t)b * 1024);
        float4*       o4 = (float4*)(out_alpha + (size_t)b * 1024);
        o4[t] = a4[t];
    }
    if (t < HH) {
        xin[t] = (t < DIN) ? x[b * DIN + t] : top[b * 4 + (t - DIN)];
        hS[t]  = h[b * HH + t];
    }
    if (t < 16) g_alphaT[b * 16 + t] = 0.f;
    if (t == 0) g_esum[b] = 0.f;
    __syncthreads();

    #pragma unroll
    for (int j = 0; j < 12; j++) {
        const int r = w + 16 * j;
        const float* wi = Wih + (size_t)r * HH;
        const float* wh = Whh + (size_t)r * HH;
        float acc = 0.f;
        #pragma unroll
        for (int k = lane; k < HH; k += 32)
            acc += xin[k] * wi[k] + hS[k] * wh[k];
        #pragma unroll
        for (int o = 16; o > 0; o >>= 1)
            acc += __shfl_xor_sync(0xffffffffu, acc, o);
        if (lane == 0) {
            const float hv = tanhf(acc + bih[r] + bhh[r]);
            g_hn[b * HH + r] = hv;
            out_h[b * HH + r] = hv;
        }
    }
}

// ---------------------------------------------------------------------------
// K1b: logits tile (64 rows) -> unnormalized exp, esum atomic.
// grid (9, 64). Blocks with n0==4 additionally compute g_tmp (old k2).
// ---------------------------------------------------------------------------
__global__ void __launch_bounds__(256) k1b_logits(
    const float* __restrict__ Wlin, const float* __restrict__ blin,
    const float* __restrict__ gamma, const int* __restrict__ tsp)
{
    const int n0 = blockIdx.x;            // 0..8
    const int b  = blockIdx.y;
    const int t  = threadIdx.x;
    const int w  = t >> 5, lane = t & 31;

    __shared__ float hnS[HH];
    __shared__ float eS[64];              // this tile's unnormalized exps
    __shared__ float wSum[8];
    __shared__ float4 gS[256];            // 4 gamma tiles for tmp stage

    if (t < HH) hnS[t] = g_hn[b * HH + t];
    __syncthreads();

    float warpSum = 0.f;
    #pragma unroll
    for (int j = 0; j < 8; j++) {
        const int la = w + 8 * j;         // local row 0..63
        const int a  = n0 * 64 + la;
        const float* wl = Wlin + (size_t)a * HH;
        float s = 0.f;
        #pragma unroll
        for (int k = lane; k < HH; k += 32)
            s += hnS[k] * wl[k];
        #pragma unroll
        for (int o = 16; o > 0; o >>= 1)
            s += __shfl_xor_sync(0xffffffffu, s, o);
        if (lane == 0) {
            const float e = expf(s + blin[a]);
            g_actions[b * NACT + a] = e;
            eS[la] = e;
            warpSum += e;
        }
    }
    if (lane == 0) wSum[w] = warpSum;
    __syncthreads();
    if (t == 0) {
        float s = 0.f;
        #pragma unroll
        for (int j = 0; j < 8; j++) s += wSum[j];
        atomicAdd(&g_esum[b], s);
    }

    if (n0 != 4) return;                  // only pop-tile blocks do tmp
    __syncthreads();                      // eS (pop values) ready

    const int ts = tsp[0] + 1;
    const float* gbase = gamma + ((size_t)b * 64) * 16384
                               + (size_t)(ts - 1) * 256;
    const int u = (t >> 4) & 3, y = (t >> 2) & 3, r = t & 3;
    const int kg = t >> 6;                // 0..3

    for (int k0 = 0; k0 < 64; k0 += 4) {
        const int kk = k0 + kg;
        gS[t] = ((const float4*)(gbase + (size_t)kk * 16384))[t & 63];
        __syncthreads();
        const float* g = (const float*)(gS + kg * 64) + u * 64 + y * 16;
        float s = 0.f;
        #pragma unroll
        for (int sz = 0; sz < 16; sz++)
            s += g[sz] * eS[(sz >> 2) * 16 + (sz & 3) * 4 + r];
        g_tmp[((size_t)b * 64 + kk) * 64 + (t & 63)] = s;
        __syncthreads();
    }
}

// ---------------------------------------------------------------------------
// K3: fused gamma row copy + gamma_t (scaled by 1/esum) + alpha_t + epilogue
// ---------------------------------------------------------------------------
__global__ void __launch_bounds__(TILE) k3_main(
    const float* __restrict__ gamma, const float* __restrict__ alpha,
    const int* __restrict__ tsp, float* __restrict__ out_gamma,
    float* __restrict__ out_alpha, float* __restrict__ out_obs)
{
    const int ts = tsp[0] + 1;
    const int bi = blockIdx.x;
    const int b  = bi >> 6;
    const int i  = bi & 63;
    const int t  = threadIdx.x;

    const size_t row = (size_t)bi << 14;
    const float4* in4  = (const float4*)(gamma + row);
    float4*       out4 = (float4*)(out_gamma + row);

    __shared__ float4 redS[TILE];
    __shared__ float  gcolS[TILE];
    __shared__ float  replT[TILE];
    __shared__ int    lastFlag;

    gcolS[t] = gamma[row + (size_t)(ts - 1) * TILE + t];
    {
        const int sz = t >> 4, y = (t >> 2) & 3, r = t & 3;
        replT[t] = g_actions[b * NACT + 320 + sz * 16 + r * 4 + y];
    }

    #pragma unroll
    for (int hB = 0; hB < 2; hB++) {
        float4 v[8];
        #pragma unroll
        for (int u2 = 0; u2 < 8; u2++) v[u2] = in4[(hB * 8 + u2) * 256 + t];
        #pragma unroll
        for (int u2 = 0; u2 < 8; u2++) {
            const int j = (hB * 8 + u2) * 256 + t;
            if ((j >> 6) != ts) out4[j] = v[u2];
        }
    }
    __syncthreads();

    const int qy = t & 63;
    const int kq = t >> 6;
    const int qx = qy >> 2;
    const int y  = qy & 3;

    float4 acc = make_float4(0.f, 0.f, 0.f, 0.f);

    {
        const float*  gk = gamma + row + qx * 16 + y;
        const float*  tb = g_tmp + (size_t)b * (Tt * 64) + y * 4;
        for (int k = i + 1 + kq; k <= ts - 2; k += 4) {
            const float*  g  = gk + k * TILE;
            const float4* tm = (const float4*)(tb + k * 64);
            #pragma unroll
            for (int u = 0; u < 4; u++) {
                const float  gv = g[u * 4];
                const float4 t4 = tm[u * 4];
                acc.x += gv * t4.x; acc.y += gv * t4.y;
                acc.z += gv * t4.z; acc.w += gv * t4.w;
            }
        }
    }

    #pragma unroll
    for (int s2 = 0; s2 < 4; s2++) {
        const int   sz = kq * 4 + s2;
        const float gv = gcolS[qx * 16 + sz];
        const float4 t4 = *(const float4*)(replT + sz * 16 + y * 4);
        acc.x += gv * t4.x; acc.y += gv * t4.y;
        acc.z += gv * t4.z; acc.w += gv * t4.w;
    }

    redS[t] = acc;
    __syncthreads();

    if (t < 64) {
        const float4 a0 = redS[t],       a1 = redS[64 + t];
        const float4 a2 = redS[128 + t], a3 = redS[192 + t];
        float4 s;
        s.x = a0.x + a1.x + a2.x + a3.x;
        s.y = a0.y + a1.y + a2.y + a3.y;
        s.z = a0.z + a1.z + a2.z + a3.z;
        s.w = a0.w + a1.w + a2.w + a3.w;

        if (i == ts - 1) {
            const float* pa = g_actions + b * NACT + qx * 16 + y;
            s.x += pa[0]; s.y += pa[4]; s.z += pa[8]; s.w += pa[12];
        }

        const float invS = 1.f / g_esum[b];   // deferred softmax normalization
        s.x *= invS; s.y *= invS; s.z *= invS; s.w *= invS;

        float* o = out_gamma + row + (size_t)ts * TILE + qx * 16 + y;
        o[0] = s.x; o[4] = s.y; o[8] = s.z; o[12] = s.w;

        const float av = alpha[bi * 16 + qx];
        redS[t] = make_float4(av * s.x, av * s.y, av * s.z, av * s.w);
    }
    __syncthreads();

    if (t < 16) {
        const int r = t >> 2, yy = t & 3;
        const float* rf = (const float*)redS;
        float s = 0.f;
        #pragma unroll
        for (int q = 0; q < 16; q++) s += rf[(q * 4 + yy) * 4 + r];
        atomicAdd(&g_alphaT[b * 16 + t], s);
        __threadfence();
    }
    __syncthreads();

    if (t == 0) {
        const unsigned int c = atomicAdd(&g_done, 1u);
        lastFlag = (c == (unsigned int)(gridDim.x - 1)) ? 1 : 0;
    }
    __syncthreads();

    if (lastFlag) {
        __threadfence();
        if (t < 64) {
            volatile const float* ga = g_alphaT + t * 16;
            float sy[4] = {0.f, 0.f, 0.f, 0.f};
            float tot = 0.f;
            #pragma unroll
            for (int j = 0; j < 16; j++) {
                const float v = ga[j];
                out_alpha[(size_t)t * 1024 + ts * 16 + j] = v;
                sy[j & 3] += v; tot += v;
            }
            const float inv2 = 1.f / (tot + 1e-5f);
            #pragma unroll
            for (int yy = 0; yy < 4; yy++) out_obs[t * 4 + yy] = sy[yy] * inv2;
        }
        if (t == 0) g_done = 0;
    }
}

// ---------------------------------------------------------------------------
extern "C" void kernel_launch(void* const* d_in, const int* in_sizes, int n_in,
                              void* d_out, int out_size)
{
    const float* x     = (const float*)d_in[0];
    const float* h     = (const float*)d_in[1];
    const float* gamma = (const float*)d_in[2];
    const float* alpha = (const float*)d_in[3];
    const float* top   = (const float*)d_in[4];
    const float* Wih   = (const float*)d_in[5];
    const float* bih   = (const float*)d_in[6];
    const float* Whh   = (const float*)d_in[7];
    const float* bhh   = (const float*)d_in[8];
    const float* Wlin  = (const float*)d_in[9];
    const float* blin  = (const float*)d_in[10];
    const int*   tsp   = (const int*)d_in[11];

    float* out = (float*)d_out;
    float* out_h     = out;
    float* out_gamma = out + (size_t)Bb * HH;
    float* out_alpha = out_gamma + (size_t)Bb * Tt * Tt * TILE;
    float* out_obs   = out_alpha + (size_t)Bb * Tt * 16;

    k1a_rnn<<<Bb, 512>>>(x, h, top, Wih, bih, Whh, bhh, alpha,
                         out_h, out_alpha);
    k1b_logits<<<dim3(9, Bb), 256>>>(Wlin, blin, gamma, tsp);
    k3_main<<<Bb * Tt, TILE>>>(gamma, alpha, tsp, out_gamma,
                               out_alpha, out_obs);
}

// round 10
// speedup vs baseline: 1.2979x; 1.2979x over previous
#include <cuda_runtime.h>
#include <cstddef>

#define Bb   64
#define Tt   64
#define DIN  188
#define HH   192
#define NACT 576       // 256 push + 64 pop + 256 repl
#define TILE 256

// Scratch
__device__ float g_actions[Bb * NACT];          // UNNORMALIZED exp(logit)
__device__ float g_esum[Bb];                    // softmax denominators
__device__ float g_hn[Bb * HH];
__device__ float g_tmp[(size_t)Bb * Tt * 64];   // tmp[b,k,u,y,r] (unnormalized)
__device__ float g_alphaT[Bb * 16];
__device__ unsigned int g_done = 0;

// ---------------------------------------------------------------------------
// K1a: h_new. grid (6, 64): block (n0,b) does rows n0*32..n0*32+31.
// 8 warps x 4 rows each -> short serial chains, 3072 warps chip-wide.
// ---------------------------------------------------------------------------
__global__ void __launch_bounds__(256) k1a_rnn(
    const float* __restrict__ x, const float* __restrict__ h,
    const float* __restrict__ top, const float* __restrict__ Wih,
    const float* __restrict__ bih, const float* __restrict__ Whh,
    const float* __restrict__ bhh, const float* __restrict__ alpha,
    float* __restrict__ out_h, float* __restrict__ out_alpha)
{
    const int n0 = blockIdx.x;            // 0..5
    const int b  = blockIdx.y;
    const int t  = threadIdx.x;
    const int w  = t >> 5, lane = t & 31;
    __shared__ float xin[HH], hS[HH];

    if (n0 == 0) {                        // one block per batch does bookkeeping
        const float4* a4 = (const float4*)(alpha + (size_t)b * 1024);
        float4*       o4 = (float4*)(out_alpha + (size_t)b * 1024);
        o4[t] = a4[t];
        if (t < 16) g_alphaT[b * 16 + t] = 0.f;
        if (t == 0) g_esum[b] = 0.f;
    }
    if (t < HH) {
        xin[t] = (t < DIN) ? x[b * DIN + t] : top[b * 4 + (t - DIN)];
        hS[t]  = h[b * HH + t];
    }
    __syncthreads();

    // 4 independent rows per warp -> ILP across rows
    float acc[4];
    #pragma unroll
    for (int jj = 0; jj < 4; jj++) acc[jj] = 0.f;
    #pragma unroll
    for (int jj = 0; jj < 4; jj++) {
        const int r = n0 * 32 + w * 4 + jj;
        const float* wi = Wih + (size_t)r * HH;
        const float* wh = Whh + (size_t)r * HH;
        #pragma unroll
        for (int k = lane; k < HH; k += 32)
            acc[jj] += xin[k] * wi[k] + hS[k] * wh[k];
    }
    #pragma unroll
    for (int jj = 0; jj < 4; jj++) {
        #pragma unroll
        for (int o = 16; o > 0; o >>= 1)
            acc[jj] += __shfl_xor_sync(0xffffffffu, acc[jj], o);
    }
    if (lane == 0) {
        #pragma unroll
        for (int jj = 0; jj < 4; jj++) {
            const int r = n0 * 32 + w * 4 + jj;
            const float hv = tanhf(acc[jj] + bih[r] + bhh[r]);
            g_hn[b * HH + r] = hv;
            out_h[b * HH + r] = hv;
        }
    }
}

// ---------------------------------------------------------------------------
// K1b: logits -> unnormalized exp + esum partial. grid (18, 64), 32-row tiles.
// ---------------------------------------------------------------------------
__global__ void __launch_bounds__(256) k1b_logits(
    const float* __restrict__ Wlin, const float* __restrict__ blin)
{
    const int n0 = blockIdx.x;            // 0..17
    const int b  = blockIdx.y;
    const int t  = threadIdx.x;
    const int w  = t >> 5, lane = t & 31;

    __shared__ float hnS[HH];
    __shared__ float wSum[8];

    if (t < HH) hnS[t] = g_hn[b * HH + t];
    __syncthreads();

    float s[4];
    #pragma unroll
    for (int jj = 0; jj < 4; jj++) s[jj] = 0.f;
    #pragma unroll
    for (int jj = 0; jj < 4; jj++) {
        const int a = n0 * 32 + w * 4 + jj;
        const float* wl = Wlin + (size_t)a * HH;
        #pragma unroll
        for (int k = lane; k < HH; k += 32)
            s[jj] += hnS[k] * wl[k];
    }
    #pragma unroll
    for (int jj = 0; jj < 4; jj++) {
        #pragma unroll
        for (int o = 16; o > 0; o >>= 1)
            s[jj] += __shfl_xor_sync(0xffffffffu, s[jj], o);
    }
    float warpSum = 0.f;
    if (lane == 0) {
        #pragma unroll
        for (int jj = 0; jj < 4; jj++) {
            const int a = n0 * 32 + w * 4 + jj;
            const float e = expf(s[jj] + blin[a]);
            g_actions[b * NACT + a] = e;
            warpSum += e;
        }
        wSum[w] = warpSum;
    }
    __syncthreads();
    if (t == 0) {
        float ss = 0.f;
        #pragma unroll
        for (int j = 0; j < 8; j++) ss += wSum[j];
        atomicAdd(&g_esum[b], ss);
    }
}

// ---------------------------------------------------------------------------
// K2: tmp[b,k,u,y,r] = sum_{s,z} gamma[b,k,ts-1,u,y,s,z] * popE[b,s,z,r]
// (unnormalized pop; k3 rescales). grid Bb*Tt, 64 threads.
// ---------------------------------------------------------------------------
__global__ void __launch_bounds__(64) k2_tmp(
    const float* __restrict__ gamma, const int* __restrict__ tsp)
{
    const int ts = tsp[0] + 1;
    const int bk = blockIdx.x;            // b*64 + k
    const int b  = bk >> 6;
    const int t  = threadIdx.x;
    __shared__ float gt[TILE], popS[64];

    const float* base = gamma + (((size_t)bk * Tt + (ts - 1)) << 8);
    #pragma unroll
    for (int j = 0; j < 4; j++) gt[t + 64 * j] = base[t + 64 * j];
    popS[t] = g_actions[b * NACT + 256 + t];
    __syncthreads();

    const int u = t >> 4, y = (t >> 2) & 3, r = t & 3;
    float s = 0.f;
    #pragma unroll
    for (int sz = 0; sz < 16; sz++) {
        const int ss = sz >> 2, z = sz & 3;
        s += gt[u * 64 + y * 16 + sz] * popS[ss * 16 + z * 4 + r];
    }
    g_tmp[(size_t)bk * 64 + t] = s;
}

// ---------------------------------------------------------------------------
// K3: fused gamma row copy + gamma_t (scaled by 1/esum) + alpha_t + epilogue
// ---------------------------------------------------------------------------
__global__ void __launch_bounds__(TILE) k3_main(
    const float* __restrict__ gamma, const float* __restrict__ alpha,
    const int* __restrict__ tsp, float* __restrict__ out_gamma,
    float* __restrict__ out_alpha, float* __restrict__ out_obs)
{
    const int ts = tsp[0] + 1;
    const int bi = blockIdx.x;
    const int b  = bi >> 6;
    const int i  = bi & 63;
    const int t  = threadIdx.x;

    const size_t row = (size_t)bi << 14;
    const float4* in4  = (const float4*)(gamma + row);
    float4*       out4 = (float4*)(out_gamma + row);

    __shared__ float4 redS[TILE];
    __shared__ float  gcolS[TILE];
    __shared__ float  replT[TILE];
    __shared__ int    lastFlag;

    gcolS[t] = gamma[row + (size_t)(ts - 1) * TILE + t];
    {
        const int sz = t >> 4, y = (t >> 2) & 3, r = t & 3;
        replT[t] = g_actions[b * NACT + 320 + sz * 16 + r * 4 + y];
    }

    #pragma unroll
    for (int hB = 0; hB < 2; hB++) {
        float4 v[8];
        #pragma unroll
        for (int u2 = 0; u2 < 8; u2++) v[u2] = in4[(hB * 8 + u2) * 256 + t];
        #pragma unroll
        for (int u2 = 0; u2 < 8; u2++) {
            const int j = (hB * 8 + u2) * 256 + t;
            if ((j >> 6) != ts) out4[j] = v[u2];
        }
    }
    __syncthreads();

    const int qy = t & 63;
    const int kq = t >> 6;
    const int qx = qy >> 2;
    const int y  = qy & 3;

    float4 acc = make_float4(0.f, 0.f, 0.f, 0.f);

    {
        const float*  gk = gamma + row + qx * 16 + y;
        const float*  tb = g_tmp + (size_t)b * (Tt * 64) + y * 4;
        for (int k = i + 1 + kq; k <= ts - 2; k += 4) {
            const float*  g  = gk + k * TILE;
            const float4* tm = (const float4*)(tb + k * 64);
            #pragma unroll
            for (int u = 0; u < 4; u++) {
                const float  gv = g[u * 4];
                const float4 t4 = tm[u * 4];
                acc.x += gv * t4.x; acc.y += gv * t4.y;
                acc.z += gv * t4.z; acc.w += gv * t4.w;
            }
        }
    }

    #pragma unroll
    for (int s2 = 0; s2 < 4; s2++) {
        const int   sz = kq * 4 + s2;
        const float gv = gcolS[qx * 16 + sz];
        const float4 t4 = *(const float4*)(replT + sz * 16 + y * 4);
        acc.x += gv * t4.x; acc.y += gv * t4.y;
        acc.z += gv * t4.z; acc.w += gv * t4.w;
    }

    redS[t] = acc;
    __syncthreads();

    if (t < 64) {
        const float4 a0 = redS[t],       a1 = redS[64 + t];
        const float4 a2 = redS[128 + t], a3 = redS[192 + t];
        float4 s;
        s.x = a0.x + a1.x + a2.x + a3.x;
        s.y = a0.y + a1.y + a2.y + a3.y;
        s.z = a0.z + a1.z + a2.z + a3.z;
        s.w = a0.w + a1.w + a2.w + a3.w;

        if (i == ts - 1) {
            const float* pa = g_actions + b * NACT + qx * 16 + y;
            s.x += pa[0]; s.y += pa[4]; s.z += pa[8]; s.w += pa[12];
        }

        const float invS = 1.f / g_esum[b];   // deferred softmax normalization
        s.x *= invS; s.y *= invS; s.z *= invS; s.w *= invS;

        float* o = out_gamma + row + (size_t)ts * TILE + qx * 16 + y;
        o[0] = s.x; o[4] = s.y; o[8] = s.z; o[12] = s.w;

        const float av = alpha[bi * 16 + qx];
        redS[t] = make_float4(av * s.x, av * s.y, av * s.z, av * s.w);
    }
    __syncthreads();

    if (t < 16) {
        const int r = t >> 2, yy = t & 3;
        const float* rf = (const float*)redS;
        float s = 0.f;
        #pragma unroll
        for (int q = 0; q < 16; q++) s += rf[(q * 4 + yy) * 4 + r];
        atomicAdd(&g_alphaT[b * 16 + t], s);
        __threadfence();
    }
    __syncthreads();

    if (t == 0) {
        const unsigned int c = atomicAdd(&g_done, 1u);
        lastFlag = (c == (unsigned int)(gridDim.x - 1)) ? 1 : 0;
    }
    __syncthreads();

    if (lastFlag) {
        __threadfence();
        if (t < 64) {
            volatile const float* ga = g_alphaT + t * 16;
            float sy[4] = {0.f, 0.f, 0.f, 0.f};
            float tot = 0.f;
            #pragma unroll
            for (int j = 0; j < 16; j++) {
                const float v = ga[j];
                out_alpha[(size_t)t * 1024 + ts * 16 + j] = v;
                sy[j & 3] += v; tot += v;
            }
            const float inv2 = 1.f / (tot + 1e-5f);
            #pragma unroll
            for (int yy = 0; yy < 4; yy++) out_obs[t * 4 + yy] = sy[yy] * inv2;
        }
        if (t == 0) g_done = 0;
    }
}

// ---------------------------------------------------------------------------
extern "C" void kernel_launch(void* const* d_in, const int* in_sizes, int n_in,
                              void* d_out, int out_size)
{
    const float* x     = (const float*)d_in[0];
    const float* h     = (const float*)d_in[1];
    const float* gamma = (const float*)d_in[2];
    const float* alpha = (const float*)d_in[3];
    const float* top   = (const float*)d_in[4];
    const float* Wih   = (const float*)d_in[5];
    const float* bih   = (const float*)d_in[6];
    const float* Whh   = (const float*)d_in[7];
    const float* bhh   = (const float*)d_in[8];
    const float* Wlin  = (const float*)d_in[9];
    const float* blin  = (const float*)d_in[10];
    const int*   tsp   = (const int*)d_in[11];

    float* out = (float*)d_out;
    float* out_h     = out;
    float* out_gamma = out + (size_t)Bb * HH;
    float* out_alpha = out_gamma + (size_t)Bb * Tt * Tt * TILE;
    float* out_obs   = out_alpha + (size_t)Bb * Tt * 16;

    k1a_rnn<<<dim3(6, Bb), 256>>>(x, h, top, Wih, bih, Whh, bhh, alpha,
                                  out_h, out_alpha);
    k1b_logits<<<dim3(18, Bb), 256>>>(Wlin, blin);
    k2_tmp<<<Bb * Tt, 64>>>(gamma, tsp);
    k3_main<<<Bb * Tt, TILE>>>(gamma, alpha, tsp, out_gamma,
                               out_alpha, out_obs);
}